// round 1
// baseline (speedup 1.0000x reference)
#include <cuda_runtime.h>
#include <cstdint>

#define N_NODES 100000
#define E_MAX   1600000
#define HID     128
#define NB_SCAN 128   // max scan blocks (ceil(100000/1024)=98)

// ---------------- device scratch (no allocations allowed) ----------------
__device__ int   g_deg[N_NODES];
__device__ int   g_rowptr[N_NODES + 1];
__device__ int   g_fill[N_NODES];
__device__ int   g_bsum[NB_SCAN];
__device__ int   g_boff[NB_SCAN];
__device__ int   g_col[E_MAX];
__device__ float g_dinv[N_NODES];
__device__ float g_tx1[(size_t)N_NODES * HID];
__device__ float g_h1 [(size_t)N_NODES * HID];
__device__ float g_h2 [(size_t)N_NODES * HID];
__device__ float g_hg [64 * HID];

// ---------------- prep ----------------
__global__ void k_zero_deg(int n) {
    int i = blockIdx.x * blockDim.x + threadIdx.x;
    if (i < n) g_deg[i] = 0;
}

__global__ void k_hist(const int* __restrict__ dst, int e) {
    int i = blockIdx.x * blockDim.x + threadIdx.x;
    if (i < e) atomicAdd(&g_deg[dst[i]], 1);
}

__global__ void k_scanA(int n) {
    __shared__ int s[1024];
    int tid = threadIdx.x;
    int i = blockIdx.x * 1024 + tid;
    int v = (i < n) ? g_deg[i] : 0;
    s[tid] = v;
    __syncthreads();
    for (int off = 1; off < 1024; off <<= 1) {
        int t = (tid >= off) ? s[tid - off] : 0;
        __syncthreads();
        s[tid] += t;
        __syncthreads();
    }
    if (i < n) g_rowptr[i] = s[tid] - v;          // exclusive within block
    if (tid == 1023) g_bsum[blockIdx.x] = s[1023];
}

__global__ void k_scanB(int nb) {
    __shared__ int s[NB_SCAN];
    int tid = threadIdx.x;
    int v = (tid < nb) ? g_bsum[tid] : 0;
    s[tid] = v;
    __syncthreads();
    for (int off = 1; off < NB_SCAN; off <<= 1) {
        int t = (tid >= off) ? s[tid - off] : 0;
        __syncthreads();
        s[tid] += t;
        __syncthreads();
    }
    s[tid] -= v;                                   // exclusive
    g_boff[tid] = s[tid];
}

__global__ void k_scanC(int n, int e) {
    int i = blockIdx.x * 1024 + threadIdx.x;
    if (i < n) {
        int rp = g_rowptr[i] + g_boff[i >> 10];
        g_rowptr[i] = rp;
        g_fill[i]   = rp;
        g_dinv[i]   = rsqrtf(fmaxf((float)g_deg[i], 1.0f));
        if (i == n - 1) g_rowptr[n] = e;
    }
}

__global__ void k_fill(const int* __restrict__ src, const int* __restrict__ dst, int e) {
    int i = blockIdx.x * blockDim.x + threadIdx.x;
    if (i < e) {
        int p = atomicAdd(&g_fill[dst[i]], 1);
        g_col[p] = src[i];
    }
}

// ---------------- SpMM: tx1 = -dinv[dst] * sum_{src->dst} dinv[src]*feat[src] ----------------
__global__ void k_spmm(int layer, const float* __restrict__ xin, int n) {
    const float* __restrict__ feat = (layer == 0) ? xin : g_h1;
    int row = blockIdx.x * 8 + (threadIdx.x >> 5);
    if (row >= n) return;
    int lane = threadIdx.x & 31;
    int e0 = g_rowptr[row];
    int e1 = g_rowptr[row + 1];
    float4 acc = make_float4(0.f, 0.f, 0.f, 0.f);
    for (int e = e0; e < e1; e++) {
        int s = g_col[e];
        float w = g_dinv[s];
        float4 v = *(const float4*)&feat[(size_t)s * HID + lane * 4];
        acc.x += w * v.x;
        acc.y += w * v.y;
        acc.z += w * v.z;
        acc.w += w * v.w;
    }
    float sc = -g_dinv[row];
    acc.x *= sc; acc.y *= sc; acc.z *= sc; acc.w *= sc;
    *(float4*)&g_tx1[(size_t)row * HID + lane * 4] = acc;
}

// ---------------- GEMM: C = relu([Ax | g_tx1] @ W + b), W is 256x128 row-major ----------------
#define GBM 128
#define GBK 32
__global__ __launch_bounds__(256) void k_gemm(int layer, const float* __restrict__ xin,
                                              const float* __restrict__ W,
                                              const float* __restrict__ bias, int n) {
    const float* __restrict__ Ax = (layer == 0) ? xin : g_h1;
    float* __restrict__ C = (layer == 0) ? g_h1 : g_h2;

    __shared__ float As[GBK][GBM];
    __shared__ float Ws[GBK][HID];

    int tid = threadIdx.x;
    int bm = blockIdx.x * GBM;
    int tx = tid & 15;   // 16 thread-cols (n)
    int ty = tid >> 4;   // 16 thread-rows (m)

    float acc[8][8];
#pragma unroll
    for (int i = 0; i < 8; i++)
#pragma unroll
        for (int j = 0; j < 8; j++) acc[i][j] = 0.f;

    int ar = tid >> 3;           // 0..31
    int ak = (tid & 7) * 4;      // 0..28
    int wr = tid >> 5;           // 0..7
    int wn = (tid & 31) * 4;     // 0..124

    for (int k0 = 0; k0 < 2 * HID; k0 += GBK) {
        const float* __restrict__ A = (k0 < HID) ? Ax : g_tx1;
        int kb = k0 & (HID - 1);

        // load A tile (transposed into smem, k-major)
#pragma unroll
        for (int p = 0; p < 4; p++) {
            int row = bm + ar + p * 32;
            float4 v = make_float4(0.f, 0.f, 0.f, 0.f);
            if (row < n) v = *(const float4*)&A[(size_t)row * HID + kb + ak];
            As[ak + 0][ar + p * 32] = v.x;
            As[ak + 1][ar + p * 32] = v.y;
            As[ak + 2][ar + p * 32] = v.z;
            As[ak + 3][ar + p * 32] = v.w;
        }
        // load W tile
#pragma unroll
        for (int p = 0; p < 4; p++) {
            *(float4*)&Ws[wr + p * 8][wn] = *(const float4*)&W[(size_t)(k0 + wr + p * 8) * HID + wn];
        }
        __syncthreads();

#pragma unroll
        for (int kk = 0; kk < GBK; kk++) {
            float a[8], b[8];
            *(float4*)(a)     = *(const float4*)&As[kk][ty * 8];
            *(float4*)(a + 4) = *(const float4*)&As[kk][ty * 8 + 4];
            *(float4*)(b)     = *(const float4*)&Ws[kk][tx * 8];
            *(float4*)(b + 4) = *(const float4*)&Ws[kk][tx * 8 + 4];
#pragma unroll
            for (int i = 0; i < 8; i++)
#pragma unroll
                for (int j = 0; j < 8; j++) acc[i][j] += a[i] * b[j];
        }
        __syncthreads();
    }

    // epilogue: bias + relu
#pragma unroll
    for (int i = 0; i < 8; i++) {
        int row = bm + ty * 8 + i;
        if (row < n) {
#pragma unroll
            for (int j = 0; j < 8; j++) {
                int col = tx * 8 + j;
                float v = acc[i][j] + bias[col];
                C[(size_t)row * HID + col] = fmaxf(v, 0.f);
            }
        }
    }
}

// ---------------- segment max over contiguous graph blocks ----------------
__global__ void k_segmax(int gsize) {
    __shared__ float sm[8][HID];
    int g = blockIdx.x;
    int warp = threadIdx.x >> 5;
    int lane = threadIdx.x & 31;
    float4 m = make_float4(0.f, 0.f, 0.f, 0.f);  // relu output >= 0
    int r0 = g * gsize;
    for (int r = r0 + warp; r < r0 + gsize; r += 8) {
        float4 v = *(const float4*)&g_h2[(size_t)r * HID + lane * 4];
        m.x = fmaxf(m.x, v.x);
        m.y = fmaxf(m.y, v.y);
        m.z = fmaxf(m.z, v.z);
        m.w = fmaxf(m.w, v.w);
    }
    *(float4*)&sm[warp][lane * 4] = m;
    __syncthreads();
    if (threadIdx.x < HID) {
        int f = threadIdx.x;
        float mm = sm[0][f];
#pragma unroll
        for (int w = 1; w < 8; w++) mm = fmaxf(mm, sm[w][f]);
        g_hg[g * HID + f] = mm;
    }
}

// ---------------- classifier head ----------------
__global__ void k_final(const float* __restrict__ Wc, const float* __restrict__ bc,
                        float* __restrict__ out, int nb) {
    int t = blockIdx.x * blockDim.x + threadIdx.x;
    if (t >= nb * 10) return;
    int g = t / 10;
    int c = t % 10;
    float acc = bc[c];
#pragma unroll 8
    for (int k = 0; k < HID; k++) acc += g_hg[g * HID + k] * Wc[k * 10 + c];
    out[t] = acc;
}

// ---------------- launch ----------------
extern "C" void kernel_launch(void* const* d_in, const int* in_sizes, int n_in,
                              void* d_out, int out_size) {
    const float* x   = (const float*)d_in[0];
    const float* W1  = (const float*)d_in[1];
    const float* b1  = (const float*)d_in[2];
    const float* W2  = (const float*)d_in[3];
    const float* b2  = (const float*)d_in[4];
    const float* Wc  = (const float*)d_in[5];
    const float* bc  = (const float*)d_in[6];
    const int*   src = (const int*)d_in[7];
    const int*   dst = (const int*)d_in[8];
    float* out = (float*)d_out;

    int e = in_sizes[7];
    int n = in_sizes[9];
    int nb_graphs = out_size / 10;
    int gsize = n / nb_graphs;
    int nbscan = (n + 1023) / 1024;

    k_zero_deg<<<(n + 511) / 512, 512>>>(n);
    k_hist<<<(e + 511) / 512, 512>>>(dst, e);
    k_scanA<<<nbscan, 1024>>>(n);
    k_scanB<<<1, NB_SCAN>>>(nbscan);
    k_scanC<<<nbscan, 1024>>>(n, e);
    k_fill<<<(e + 511) / 512, 512>>>(src, dst, e);

    // layer 1
    k_spmm<<<(n + 7) / 8, 256>>>(0, x, n);
    k_gemm<<<(n + GBM - 1) / GBM, 256>>>(0, x, W1, b1, n);
    // layer 2
    k_spmm<<<(n + 7) / 8, 256>>>(1, x, n);
    k_gemm<<<(n + GBM - 1) / GBM, 256>>>(1, x, W2, b2, n);

    k_segmax<<<nb_graphs, 256>>>(gsize);
    k_final<<<1, 512>>>(Wc, bc, out, nb_graphs);
}

// round 2
// speedup vs baseline: 1.7038x; 1.7038x over previous
#include <cuda_runtime.h>
#include <cstdint>

#define N_NODES 100000
#define E_MAX   1600000
#define HID     128
#define NB_SCAN 128

typedef unsigned long long u64t;

// ---------------- device scratch (no allocations allowed) ----------------
__device__ int   g_deg[N_NODES];
__device__ int   g_rowptr[N_NODES + 1];
__device__ int   g_fill[N_NODES];
__device__ int   g_bsum[NB_SCAN];
__device__ int   g_boff[NB_SCAN];
__device__ int   g_col[E_MAX];
__device__ float g_dinv[N_NODES];
__device__ float g_tx1[(size_t)N_NODES * HID];
__device__ float g_h1 [(size_t)N_NODES * HID];
__device__ float g_h2 [(size_t)N_NODES * HID];
__device__ float g_hg [64 * HID];

// ---------------- packed f32x2 helpers ----------------
__device__ __forceinline__ void ffma2(u64t &d, u64t a, u64t b) {
    asm("fma.rn.f32x2 %0, %1, %2, %0;" : "+l"(d) : "l"(a), "l"(b));
}
__device__ __forceinline__ u64t dup2(float x) {
    u64t r; asm("mov.b64 %0, {%1, %1};" : "=l"(r) : "f"(x)); return r;
}
__device__ __forceinline__ float2 unpack2(u64t v) {
    float2 f; asm("mov.b64 {%0, %1}, %2;" : "=f"(f.x), "=f"(f.y) : "l"(v)); return f;
}

// ---------------- prep ----------------
__global__ void k_zero_deg(int n) {
    int i = blockIdx.x * blockDim.x + threadIdx.x;
    if (i < n) g_deg[i] = 0;
}

__global__ void k_hist(const int* __restrict__ dst, int e) {
    int i = blockIdx.x * blockDim.x + threadIdx.x;
    if (i < e) atomicAdd(&g_deg[dst[i]], 1);
}

__global__ void k_scanA(int n) {
    __shared__ int s[1024];
    int tid = threadIdx.x;
    int i = blockIdx.x * 1024 + tid;
    int v = (i < n) ? g_deg[i] : 0;
    s[tid] = v;
    __syncthreads();
    for (int off = 1; off < 1024; off <<= 1) {
        int t = (tid >= off) ? s[tid - off] : 0;
        __syncthreads();
        s[tid] += t;
        __syncthreads();
    }
    if (i < n) g_rowptr[i] = s[tid] - v;
    if (tid == 1023) g_bsum[blockIdx.x] = s[1023];
}

__global__ void k_scanB(int nb) {
    __shared__ int s[NB_SCAN];
    int tid = threadIdx.x;
    int v = (tid < nb) ? g_bsum[tid] : 0;
    s[tid] = v;
    __syncthreads();
    for (int off = 1; off < NB_SCAN; off <<= 1) {
        int t = (tid >= off) ? s[tid - off] : 0;
        __syncthreads();
        s[tid] += t;
        __syncthreads();
    }
    s[tid] -= v;
    g_boff[tid] = s[tid];
}

__global__ void k_scanC(int n, int e) {
    int i = blockIdx.x * 1024 + threadIdx.x;
    if (i < n) {
        int rp = g_rowptr[i] + g_boff[i >> 10];
        g_rowptr[i] = rp;
        g_fill[i]   = rp;
        g_dinv[i]   = rsqrtf(fmaxf((float)g_deg[i], 1.0f));
        if (i == n - 1) g_rowptr[n] = e;
    }
}

__global__ void k_fill(const int* __restrict__ src, const int* __restrict__ dst, int e) {
    int i = blockIdx.x * blockDim.x + threadIdx.x;
    if (i < e) {
        int p = atomicAdd(&g_fill[dst[i]], 1);
        g_col[p] = src[i];
    }
}

// ---------------- SpMM: tx1 = -dinv[dst] * sum_{src->dst} dinv[src]*feat[src] ----------------
__global__ void k_spmm(int layer, const float* __restrict__ xin, int n) {
    const float* __restrict__ feat = (layer == 0) ? xin : g_h1;
    int row = blockIdx.x * 8 + (threadIdx.x >> 5);
    if (row >= n) return;
    int lane = threadIdx.x & 31;
    int e0 = g_rowptr[row];
    int e1 = g_rowptr[row + 1];
    float4 acc = make_float4(0.f, 0.f, 0.f, 0.f);
    for (int e = e0; e < e1; e++) {
        int s = g_col[e];
        float w = g_dinv[s];
        float4 v = *(const float4*)&feat[(size_t)s * HID + lane * 4];
        acc.x += w * v.x;
        acc.y += w * v.y;
        acc.z += w * v.z;
        acc.w += w * v.w;
    }
    float sc = -g_dinv[row];
    acc.x *= sc; acc.y *= sc; acc.z *= sc; acc.w *= sc;
    *(float4*)&g_tx1[(size_t)row * HID + lane * 4] = acc;
}

// ---------------- GEMM: C = relu([Ax | g_tx1] @ W + b), W is 256x128 row-major ----------------
// Inner product uses packed fma.rn.f32x2 (2 fp32 FMAs per FMA-pipe slot).
#define GBM 128
#define GBK 32
__global__ __launch_bounds__(256) void k_gemm(int layer, const float* __restrict__ xin,
                                              const float* __restrict__ W,
                                              const float* __restrict__ bias, int n) {
    const float* __restrict__ Ax = (layer == 0) ? xin : g_h1;
    float* __restrict__ C = (layer == 0) ? g_h1 : g_h2;

    __shared__ float As[GBK][GBM];
    __shared__ float Ws[GBK][HID];

    int tid = threadIdx.x;
    int bm = blockIdx.x * GBM;
    int tx = tid & 15;   // 16 thread-cols (n)
    int ty = tid >> 4;   // 16 thread-rows (m)

    u64t acc2[8][4];
#pragma unroll
    for (int i = 0; i < 8; i++)
#pragma unroll
        for (int j = 0; j < 4; j++) acc2[i][j] = 0ull;

    int ar = tid >> 3;           // 0..31
    int ak = (tid & 7) * 4;      // 0..28
    int wr = tid >> 5;           // 0..7
    int wn = (tid & 31) * 4;     // 0..124

    for (int k0 = 0; k0 < 2 * HID; k0 += GBK) {
        const float* __restrict__ A = (k0 < HID) ? Ax : g_tx1;
        int kb = k0 & (HID - 1);

        // load A tile (transposed into smem, k-major)
#pragma unroll
        for (int p = 0; p < 4; p++) {
            int row = bm + ar + p * 32;
            float4 v = make_float4(0.f, 0.f, 0.f, 0.f);
            if (row < n) v = *(const float4*)&A[(size_t)row * HID + kb + ak];
            As[ak + 0][ar + p * 32] = v.x;
            As[ak + 1][ar + p * 32] = v.y;
            As[ak + 2][ar + p * 32] = v.z;
            As[ak + 3][ar + p * 32] = v.w;
        }
        // load W tile
#pragma unroll
        for (int p = 0; p < 4; p++) {
            *(float4*)&Ws[wr + p * 8][wn] = *(const float4*)&W[(size_t)(k0 + wr + p * 8) * HID + wn];
        }
        __syncthreads();

#pragma unroll
        for (int kk = 0; kk < GBK; kk++) {
            float a[8];
            u64t b2[4];
            *(float4*)(a)     = *(const float4*)&As[kk][ty * 8];
            *(float4*)(a + 4) = *(const float4*)&As[kk][ty * 8 + 4];
            ulonglong2 t0 = *(const ulonglong2*)&Ws[kk][tx * 8];
            ulonglong2 t1 = *(const ulonglong2*)&Ws[kk][tx * 8 + 4];
            b2[0] = t0.x; b2[1] = t0.y; b2[2] = t1.x; b2[3] = t1.y;
#pragma unroll
            for (int i = 0; i < 8; i++) {
                u64t ad = dup2(a[i]);
#pragma unroll
                for (int j = 0; j < 4; j++) ffma2(acc2[i][j], ad, b2[j]);
            }
        }
        __syncthreads();
    }

    // epilogue: bias + relu
#pragma unroll
    for (int i = 0; i < 8; i++) {
        int row = bm + ty * 8 + i;
        if (row < n) {
#pragma unroll
            for (int j = 0; j < 4; j++) {
                float2 f = unpack2(acc2[i][j]);
                int col = tx * 8 + j * 2;
                float v0 = f.x + bias[col];
                float v1 = f.y + bias[col + 1];
                C[(size_t)row * HID + col]     = fmaxf(v0, 0.f);
                C[(size_t)row * HID + col + 1] = fmaxf(v1, 0.f);
            }
        }
    }
}

// ---------------- segment max over contiguous graph blocks ----------------
__global__ void k_segmax(int gsize) {
    __shared__ float sm[8][HID];
    int g = blockIdx.x;
    int warp = threadIdx.x >> 5;
    int lane = threadIdx.x & 31;
    float4 m = make_float4(0.f, 0.f, 0.f, 0.f);  // relu output >= 0
    int r0 = g * gsize;
    for (int r = r0 + warp; r < r0 + gsize; r += 8) {
        float4 v = *(const float4*)&g_h2[(size_t)r * HID + lane * 4];
        m.x = fmaxf(m.x, v.x);
        m.y = fmaxf(m.y, v.y);
        m.z = fmaxf(m.z, v.z);
        m.w = fmaxf(m.w, v.w);
    }
    *(float4*)&sm[warp][lane * 4] = m;
    __syncthreads();
    if (threadIdx.x < HID) {
        int f = threadIdx.x;
        float mm = sm[0][f];
#pragma unroll
        for (int w = 1; w < 8; w++) mm = fmaxf(mm, sm[w][f]);
        g_hg[g * HID + f] = mm;
    }
}

// ---------------- classifier head ----------------
__global__ void k_final(const float* __restrict__ Wc, const float* __restrict__ bc,
                        float* __restrict__ out, int nb) {
    int t = blockIdx.x * blockDim.x + threadIdx.x;
    if (t >= nb * 10) return;
    int g = t / 10;
    int c = t % 10;
    float acc = bc[c];
#pragma unroll 8
    for (int k = 0; k < HID; k++) acc += g_hg[g * HID + k] * Wc[k * 10 + c];
    out[t] = acc;
}

// ---------------- launch ----------------
extern "C" void kernel_launch(void* const* d_in, const int* in_sizes, int n_in,
                              void* d_out, int out_size) {
    const float* x   = (const float*)d_in[0];
    const float* W1  = (const float*)d_in[1];
    const float* b1  = (const float*)d_in[2];
    const float* W2  = (const float*)d_in[3];
    const float* b2  = (const float*)d_in[4];
    const float* Wc  = (const float*)d_in[5];
    const float* bc  = (const float*)d_in[6];
    const int*   src = (const int*)d_in[7];
    const int*   dst = (const int*)d_in[8];
    float* out = (float*)d_out;

    int e = in_sizes[7];
    int n = in_sizes[9];
    int nb_graphs = out_size / 10;
    int gsize = n / nb_graphs;
    int nbscan = (n + 1023) / 1024;

    k_zero_deg<<<(n + 511) / 512, 512>>>(n);
    k_hist<<<(e + 511) / 512, 512>>>(dst, e);
    k_scanA<<<nbscan, 1024>>>(n);
    k_scanB<<<1, NB_SCAN>>>(nbscan);
    k_scanC<<<nbscan, 1024>>>(n, e);
    k_fill<<<(e + 511) / 512, 512>>>(src, dst, e);

    // layer 1
    k_spmm<<<(n + 7) / 8, 256>>>(0, x, n);
    k_gemm<<<(n + GBM - 1) / GBM, 256>>>(0, x, W1, b1, n);
    // layer 2
    k_spmm<<<(n + 7) / 8, 256>>>(1, x, n);
    k_gemm<<<(n + GBM - 1) / GBM, 256>>>(1, x, W2, b2, n);

    k_segmax<<<nb_graphs, 256>>>(gsize);
    k_final<<<1, 512>>>(Wc, bc, out, nb_graphs);
}